// round 5
// baseline (speedup 1.0000x reference)
#include <cuda_runtime.h>

#define B_SZ 512
#define D_SZ 1024
#define P_SZ 16
#define N_SZ 128
#define ALPHA_F 0.8f
#define NROWS 145                 // row 0 = tgt, 1..16 = rel, 17..144 = irr
#define SPLIT 8
#define NBLOCKS (B_SZ * SPLIT)    // 4096
#define TPB 128

__device__ float g_pos[NBLOCKS];
__device__ float g_neg[NBLOCKS];
__device__ float g_diag[B_SZ];
__device__ unsigned int g_count = 0;

__device__ __forceinline__ const float4*
row_ptr(const float* __restrict__ tgt, const float* __restrict__ rel,
        const float* __restrict__ irr, int b, int r)
{
    const float* p;
    if (r == 0)
        p = tgt + (size_t)b * D_SZ;
    else if (r <= P_SZ)
        p = rel + ((size_t)b * P_SZ + (r - 1)) * D_SZ;
    else
        p = irr + ((size_t)b * N_SZ + (r - 1 - P_SZ)) * D_SZ;
    return reinterpret_cast<const float4*>(p);
}

__global__ void __launch_bounds__(TPB, 8)
contrastive_loss_kernel(const float* __restrict__ src,
                        const float* __restrict__ tgt,
                        const float* __restrict__ rel,
                        const float* __restrict__ irr,
                        float* __restrict__ out)
{
    __shared__ float4 s_srcv[D_SZ / 4];
    __shared__ float  s_red[4];
    __shared__ float  s_pos[4];
    __shared__ float  s_neg[4];
    __shared__ float  s_inv;
    __shared__ int    s_last;

    const int blk  = blockIdx.x;
    const int b    = blk >> 3;            // batch row
    const int s    = blk & 7;             // split index
    const int tid  = threadIdx.x;
    const int wid  = tid >> 5;
    const int lane = tid & 31;

    // ---- prologue: src row -> smem, sum of squares ----
    const float4* srcv = reinterpret_cast<const float4*>(src + (size_t)b * D_SZ);
    float ss = 0.f;
    #pragma unroll
    for (int i = 0; i < 2; i++) {
        int idx = i * TPB + tid;
        float4 v = srcv[idx];
        s_srcv[idx] = v;
        ss += v.x * v.x + v.y * v.y + v.z * v.z + v.w * v.w;
    }
    #pragma unroll
    for (int o = 16; o > 0; o >>= 1) ss += __shfl_xor_sync(0xFFFFFFFFu, ss, o);
    if (lane == 0) s_red[wid] = ss;
    __syncthreads();
    if (tid == 0)
        s_inv = rsqrtf(fmaxf(s_red[0] + s_red[1] + s_red[2] + s_red[3], 1e-24f));
    __syncthreads();
    const float inv_src = s_inv;

    // ---- this block's slice of the 145 rows ----
    const int r0 = (s * NROWS) / SPLIT;
    const int r1 = ((s + 1) * NROWS) / SPLIT;

    float pos_acc = 0.f, neg_acc = 0.f, diag = 0.f;

    // ---- software-pipelined row loop: loads always in flight ----
    // buffers: two halves of 4 float4 each (half = 4 LDG.128 per lane)
    float4 bufA[4], bufB[4];

    int r = r0 + wid;
    if (r < r1) {
        const float4* p = row_ptr(tgt, rel, irr, b, r);
        // prime: half 0 of first row
        #pragma unroll
        for (int j = 0; j < 4; j++) bufA[j] = __ldcs(&p[j * 32 + lane]);

        while (r < r1) {
            const int rn = r + 4;                       // 4 warps per block
            // dummy prefetch target = L2-hot src row (no extra DRAM traffic)
            const float4* pn = (rn < r1) ? row_ptr(tgt, rel, irr, b, rn) : srcv;

            // issue half-1 loads, then compute half-0 FMAs
            #pragma unroll
            for (int j = 0; j < 4; j++) bufB[j] = __ldcs(&p[128 + j * 32 + lane]);

            float dot = 0.f, rss = 0.f;
            #pragma unroll
            for (int j = 0; j < 4; j++) {
                float4 v  = bufA[j];
                float4 sv = s_srcv[j * 32 + lane];
                dot += v.x * sv.x + v.y * sv.y + v.z * sv.z + v.w * sv.w;
                rss += v.x * v.x + v.y * v.y + v.z * v.z + v.w * v.w;
            }

            // issue next row's half-0 loads, then compute half-1 FMAs
            #pragma unroll
            for (int j = 0; j < 4; j++) bufA[j] = __ldcs(&pn[j * 32 + lane]);

            #pragma unroll
            for (int j = 0; j < 4; j++) {
                float4 v  = bufB[j];
                float4 sv = s_srcv[128 + j * 32 + lane];
                dot += v.x * sv.x + v.y * sv.y + v.z * sv.z + v.w * sv.w;
                rss += v.x * v.x + v.y * v.y + v.z * v.z + v.w * v.w;
            }

            // butterfly reduce — next row's half-0 loads are in flight underneath
            #pragma unroll
            for (int o = 16; o > 0; o >>= 1) {
                dot += __shfl_xor_sync(0xFFFFFFFFu, dot, o);
                rss += __shfl_xor_sync(0xFFFFFFFFu, rss, o);
            }
            if (lane == 0) {
                float c = dot * inv_src * rsqrtf(fmaxf(rss, 1e-24f));
                if (r == 0)            diag = c;
                else if (r <= P_SZ)    pos_acc += expf(c);
                else                   neg_acc += expf(c);
            }
            p = pn;
            r = rn;
        }
    }

    if (lane == 0) { s_pos[wid] = pos_acc; s_neg[wid] = neg_acc; }
    __syncthreads();

    if (tid == 0) {
        g_pos[blk] = s_pos[0] + s_pos[1] + s_pos[2] + s_pos[3];
        g_neg[blk] = s_neg[0] + s_neg[1] + s_neg[2] + s_neg[3];
        if (s == 0) g_diag[b] = diag;   // tid0 = warp0 lane0 handled row 0

        unsigned int old;
        asm volatile("atom.acq_rel.gpu.global.add.u32 %0, [%1], %2;"
                     : "=r"(old)
                     : "l"(&g_count), "r"(1u)
                     : "memory");
        s_last = (old == NBLOCKS - 1);
    }
    __syncthreads();

    // ---- last block computes the final loss ----
    if (s_last) {
        float acc = 0.f;
        #pragma unroll
        for (int it = 0; it < B_SZ / TPB; it++) {
            int bb = it * TPB + tid;
            float ps = 0.f, ns = 0.f;
            #pragma unroll
            for (int k = 0; k < SPLIT; k++) {
                ps += g_pos[bb * SPLIT + k];
                ns += g_neg[bb * SPLIT + k];
            }
            float pos_score = 1.f + ps;
            float lp = logf(pos_score);
            float ln = logf(pos_score + ns);
            acc += -(ALPHA_F * g_diag[bb] + (1.f - ALPHA_F) * (lp - ln));
        }
        #pragma unroll
        for (int o = 16; o > 0; o >>= 1) acc += __shfl_xor_sync(0xFFFFFFFFu, acc, o);
        if (lane == 0) s_red[wid] = acc;
        __syncthreads();
        if (tid == 0) {
            out[0] = (s_red[0] + s_red[1] + s_red[2] + s_red[3]) * (1.0f / (float)B_SZ);
            g_count = 0;                // reset for next graph replay
        }
    }
}

extern "C" void kernel_launch(void* const* d_in, const int* in_sizes, int n_in,
                              void* d_out, int out_size)
{
    const float* src = (const float*)d_in[0];   // [B, D]
    const float* tgt = (const float*)d_in[1];   // [B, D]
    const float* rel = (const float*)d_in[2];   // [B, P, D]
    const float* irr = (const float*)d_in[3];   // [B, N, D]
    float* out = (float*)d_out;

    contrastive_loss_kernel<<<NBLOCKS, TPB>>>(src, tgt, rel, irr, out);
}

// round 6
// speedup vs baseline: 1.0775x; 1.0775x over previous
#include <cuda_runtime.h>
#include <cstdint>

#define B_SZ 512
#define D_SZ 1024
#define P_SZ 16
#define N_SZ 128
#define ALPHA_F 0.8f
#define NROWS 145                 // row 0 = tgt, 1..16 = rel, 17..144 = irr
#define SPLIT 8
#define NBLOCKS (B_SZ * SPLIT)    // 4096
#define TPB 128
#define NWARPS 4
#define ROW_BYTES 4096            // 1024 fp32

__device__ float g_pos[NBLOCKS];
__device__ float g_neg[NBLOCKS];
__device__ float g_diag[B_SZ];
__device__ unsigned int g_count = 0;

__device__ __forceinline__ uint32_t smem_u32(const void* p) {
    uint32_t a;
    asm("{ .reg .u64 t; cvta.to.shared.u64 t, %1; cvt.u32.u64 %0, t; }"
        : "=r"(a) : "l"(p));
    return a;
}

__device__ __forceinline__ void mbar_init(uint32_t mbar, uint32_t count) {
    asm volatile("mbarrier.init.shared.b64 [%0], %1;" :: "r"(mbar), "r"(count) : "memory");
}
__device__ __forceinline__ void mbar_expect_tx(uint32_t mbar, uint32_t bytes) {
    asm volatile("mbarrier.arrive.expect_tx.shared.b64 _, [%0], %1;"
                 :: "r"(mbar), "r"(bytes) : "memory");
}
__device__ __forceinline__ void tma_row(uint32_t smem_dst, const float* gmem_src, uint32_t mbar) {
    asm volatile("cp.async.bulk.shared::cta.global.mbarrier::complete_tx::bytes "
                 "[%0], [%1], %2, [%3];"
                 :: "r"(smem_dst), "l"(gmem_src), "r"((uint32_t)ROW_BYTES), "r"(mbar)
                 : "memory");
}
__device__ __forceinline__ void mbar_wait(uint32_t mbar, uint32_t parity) {
    uint32_t done;
    asm volatile(
        "{\n\t.reg .pred p;\n\t"
        "mbarrier.try_wait.parity.acquire.cta.shared::cta.b64 p, [%1], %2;\n\t"
        "selp.b32 %0, 1, 0, p;\n\t}"
        : "=r"(done) : "r"(mbar), "r"(parity) : "memory");
    if (!done) {
        asm volatile(
            "{\n\t.reg .pred P1;\n\t"
            "W_%=:\n\t"
            "mbarrier.try_wait.parity.acquire.cta.shared::cta.b64 P1, [%0], %1, 0x989680;\n\t"
            "@P1 bra.uni D_%=;\n\t"
            "bra.uni W_%=;\n\t"
            "D_%=:\n\t}"
            :: "r"(mbar), "r"(parity) : "memory");
    }
}

__device__ __forceinline__ const float*
row_ptr(const float* __restrict__ tgt, const float* __restrict__ rel,
        const float* __restrict__ irr, int b, int r)
{
    if (r == 0)      return tgt + (size_t)b * D_SZ;
    else if (r <= P_SZ) return rel + ((size_t)b * P_SZ + (r - 1)) * D_SZ;
    else             return irr + ((size_t)b * N_SZ + (r - 1 - P_SZ)) * D_SZ;
}

__global__ void __launch_bounds__(TPB)
contrastive_loss_kernel(const float* __restrict__ src,
                        const float* __restrict__ tgt,
                        const float* __restrict__ rel,
                        const float* __restrict__ irr,
                        float* __restrict__ out)
{
    __shared__ __align__(16) float4 s_buf[NWARPS][2][ROW_BYTES / 16]; // 32 KB
    __shared__ __align__(8)  unsigned long long s_mbar[NWARPS][2];
    __shared__ float s_pos[NWARPS], s_neg[NWARPS];
    __shared__ int   s_last;

    const int blk  = blockIdx.x;
    const int b    = blk >> 3;            // batch row
    const int s    = blk & 7;             // split index
    const int tid  = threadIdx.x;
    const int wid  = tid >> 5;
    const int lane = tid & 31;

    const uint32_t mb0 = smem_u32(&s_mbar[wid][0]);
    const uint32_t mb1 = smem_u32(&s_mbar[wid][1]);
    const uint32_t sb0 = smem_u32(&s_buf[wid][0][0]);
    const uint32_t sb1 = smem_u32(&s_buf[wid][1][0]);

    // ---- per-warp mbarrier init (warp-private barriers) ----
    if (lane == 0) {
        mbar_init(mb0, 1);
        mbar_init(mb1, 1);
        asm volatile("fence.mbarrier_init.release.cluster;" ::: "memory");
    }
    __syncwarp();

    // ---- this block's slice of the 145 rows; rows for this warp: r0+wid, +4... ----
    const int r0 = (s * NROWS) / SPLIT;
    const int r1 = ((s + 1) * NROWS) / SPLIT;
    const int first = r0 + wid;
    const int nr = (first < r1) ? ((r1 - first + NWARPS - 1) / NWARPS) : 0;

    // ---- prime the TMA pipeline (depth 2) before touching src ----
    if (lane == 0) {
        if (nr > 0) {
            mbar_expect_tx(mb0, ROW_BYTES);
            tma_row(sb0, row_ptr(tgt, rel, irr, b, first), mb0);
        }
        if (nr > 1) {
            mbar_expect_tx(mb1, ROW_BYTES);
            tma_row(sb1, row_ptr(tgt, rel, irr, b, first + NWARPS), mb1);
        }
    }

    // ---- src row into registers (L2-hot); warp-local norm ----
    const float4* srcv = reinterpret_cast<const float4*>(src + (size_t)b * D_SZ);
    float4 sreg[8];
    float ss = 0.f;
    #pragma unroll
    for (int j = 0; j < 8; j++) {
        sreg[j] = __ldg(&srcv[j * 32 + lane]);
        ss += sreg[j].x * sreg[j].x + sreg[j].y * sreg[j].y
            + sreg[j].z * sreg[j].z + sreg[j].w * sreg[j].w;
    }
    #pragma unroll
    for (int o = 16; o > 0; o >>= 1) ss += __shfl_xor_sync(0xFFFFFFFFu, ss, o);
    const float inv_src = rsqrtf(fmaxf(ss, 1e-24f));   // all lanes hold it

    float pos_acc = 0.f, neg_acc = 0.f, diag = 0.f;

    uint32_t ph0 = 0, ph1 = 0;
    for (int i = 0; i < nr; i++) {
        const int k = i & 1;
        const uint32_t mb = k ? mb1 : mb0;
        const uint32_t sb = k ? sb1 : sb0;

        // wait for row i's TMA completion
        mbar_wait(mb, k ? ph1 : ph0);
        if (k) ph1 ^= 1u; else ph0 ^= 1u;

        // consume from smem (conflict-free LDS.128)
        const float4* rv = k ? &s_buf[wid][1][0] : &s_buf[wid][0][0];
        float dot = 0.f, rss = 0.f;
        #pragma unroll
        for (int j = 0; j < 8; j++) {
            float4 v = rv[j * 32 + lane];
            dot += v.x * sreg[j].x + v.y * sreg[j].y + v.z * sreg[j].z + v.w * sreg[j].w;
            rss += v.x * v.x + v.y * v.y + v.z * v.z + v.w * v.w;
        }

        // refill this buffer with row i+2 (buffer fully consumed into regs above)
        if (lane == 0 && i + 2 < nr) {
            mbar_expect_tx(mb, ROW_BYTES);
            tma_row(sb, row_ptr(tgt, rel, irr, b, first + (i + 2) * NWARPS), mb);
        }

        // reduce while the refill streams underneath
        #pragma unroll
        for (int o = 16; o > 0; o >>= 1) {
            dot += __shfl_xor_sync(0xFFFFFFFFu, dot, o);
            rss += __shfl_xor_sync(0xFFFFFFFFu, rss, o);
        }
        if (lane == 0) {
            const int r = first + i * NWARPS;
            float c = dot * inv_src * rsqrtf(fmaxf(rss, 1e-24f));
            if (r == 0)            diag = c;
            else if (r <= P_SZ)    pos_acc += expf(c);
            else                   neg_acc += expf(c);
        }
    }

    if (lane == 0) { s_pos[wid] = pos_acc; s_neg[wid] = neg_acc; }
    __syncthreads();

    if (tid == 0) {
        g_pos[blk] = s_pos[0] + s_pos[1] + s_pos[2] + s_pos[3];
        g_neg[blk] = s_neg[0] + s_neg[1] + s_neg[2] + s_neg[3];
        if (s == 0) g_diag[b] = diag;   // tid0 = warp0 lane0 handled row 0

        unsigned int old;
        asm volatile("atom.acq_rel.gpu.global.add.u32 %0, [%1], %2;"
                     : "=r"(old)
                     : "l"(&g_count), "r"(1u)
                     : "memory");
        s_last = (old == NBLOCKS - 1);
    }
    __syncthreads();

    // ---- last block computes the final loss (fused) ----
    if (s_last) {
        float acc = 0.f;
        #pragma unroll
        for (int it = 0; it < B_SZ / TPB; it++) {
            int bb = it * TPB + tid;
            float ps = 0.f, ns = 0.f;
            #pragma unroll
            for (int kk = 0; kk < SPLIT; kk++) {
                ps += g_pos[bb * SPLIT + kk];
                ns += g_neg[bb * SPLIT + kk];
            }
            float pos_score = 1.f + ps;
            float lp = logf(pos_score);
            float ln = logf(pos_score + ns);
            acc += -(ALPHA_F * g_diag[bb] + (1.f - ALPHA_F) * (lp - ln));
        }
        #pragma unroll
        for (int o = 16; o > 0; o >>= 1) acc += __shfl_xor_sync(0xFFFFFFFFu, acc, o);
        if (lane == 0) s_pos[wid] = acc;
        __syncthreads();
        if (tid == 0) {
            out[0] = (s_pos[0] + s_pos[1] + s_pos[2] + s_pos[3]) * (1.0f / (float)B_SZ);
            g_count = 0;                // reset for next graph replay
        }
    }
}

extern "C" void kernel_launch(void* const* d_in, const int* in_sizes, int n_in,
                              void* d_out, int out_size)
{
    const float* src = (const float*)d_in[0];   // [B, D]
    const float* tgt = (const float*)d_in[1];   // [B, D]
    const float* rel = (const float*)d_in[2];   // [B, P, D]
    const float* irr = (const float*)d_in[3];   // [B, N, D]
    float* out = (float*)d_out;

    contrastive_loss_kernel<<<NBLOCKS, TPB>>>(src, tgt, rel, irr, out);
}